// round 8
// baseline (speedup 1.0000x reference)
#include <cuda_runtime.h>

#define AN 76725
#define NC 80
#define CA (AN * NC)
#define CAP 2048
#define NTIER 3
#define MAXKEEP 200
#define IMGF 640.0f
#define T_A 0.9963f
#define T_B 0.99f
#define T_C 0.97f
#define NT 1024
#define NB 64
#define FULLW 0xFFFFFFFFu

// Scratch (device globals: no allocation allowed)
__device__ float g_boxes[AN * 4];  // decoded boxes
__device__ float g_area[AN];
__device__ unsigned long long g_cand[NTIER][NC][CAP];  // per-tier per-class keys
__device__ int g_cnt[NTIER][NC];
// compact per-class NMS results
__device__ int g_kcnt[NC];
__device__ float4 g_kboxg[NC][MAXKEEP];
__device__ float g_kscg[NC][MAXKEEP];
__device__ int g_kidg[NC][MAXKEEP];

// ---------------------------------------------------------------------------
// Fused prep: candidate gather (float4 over [A,C]) + box decode + cnt reset
// ---------------------------------------------------------------------------
__global__ void prep_kernel(const float* __restrict__ cls,
                            const float* __restrict__ anchors,
                            const float* __restrict__ reg) {
    int t = blockIdx.x * blockDim.x + threadIdx.x;

    // counter reset (first few threads; gather atomics below only touch counts
    // reset on a PREVIOUS launch — so reset must come from the prior kernel.
    // Instead counters are reset at the END of scatter_kernel of the previous
    // replay... not allowed (determinism). So: reset here is racy vs atomics
    // of other blocks. Solution: dedicated reset below in decode section is
    // WRONG; we keep a separate tiny reset via the fill path? No — we simply
    // have gather use a fresh epoch trick: not needed; counters are reset by
    // the decode portion of THIS kernel only if no gather atomic can run
    // before all resets. That cannot be guaranteed across blocks.
    // => Counters are instead reset by fill_kernel (launched BEFORE prep).
    // (this block intentionally left as documentation)

    // decode duty for the first AN threads
    if (t < AN) {
        int i = t;
        float a0 = anchors[i * 4 + 0], a1 = anchors[i * 4 + 1];
        float a2 = anchors[i * 4 + 2], a3 = anchors[i * 4 + 3];
        float r0 = reg[i * 4 + 0], r1 = reg[i * 4 + 1];
        float r2 = reg[i * 4 + 2], r3 = reg[i * 4 + 3];
        float aw = a2 - a0, ah = a3 - a1;
        float ax = a0 + 0.5f * aw, ay = a1 + 0.5f * ah;
        float cx = ax + r0 * 0.1f * aw;
        float cy = ay + r1 * 0.1f * ah;
        float w = aw * expf(r2 * 0.2f);
        float h = ah * expf(r3 * 0.2f);
        float x1 = fminf(fmaxf(cx - 0.5f * w, 0.0f), IMGF);
        float y1 = fminf(fmaxf(cy - 0.5f * h, 0.0f), IMGF);
        float x2 = fminf(fmaxf(cx + 0.5f * w, 0.0f), IMGF);
        float y2 = fminf(fmaxf(cy + 0.5f * h, 0.0f), IMGF);
        g_boxes[i * 4 + 0] = x1;
        g_boxes[i * 4 + 1] = y1;
        g_boxes[i * 4 + 2] = x2;
        g_boxes[i * 4 + 3] = y2;
        g_area[i] = (x2 - x1) * (y2 - y1);
    }

    // gather duty: 4 consecutive scores per thread
    if (t < CA / 4) {
        float4 v = ((const float4*)cls)[t];
        float sv[4] = {v.x, v.y, v.z, v.w};
        #pragma unroll
        for (int k = 0; k < 4; k++) {
            float s = sv[k];
            if (s > T_C) {
                int f = t * 4 + k;
                int c = f % NC;
                int a = f / NC;
                int tier = (s > T_A) ? 0 : ((s > T_B) ? 1 : 2);
                int p = atomicAdd(&g_cnt[tier][c], 1);
                if (p < CAP)
                    g_cand[tier][c][p] =
                        ((unsigned long long)__float_as_uint(s) << 32) |
                        (unsigned long long)(0xFFFFFFFFu - (unsigned)a);
            }
        }
    }
}

// ---------------------------------------------------------------------------
// Fill: streaming stores, 4 independent STG.128 per thread, exact cover.
// Also resets the candidate counters (runs before prep_kernel).
// ---------------------------------------------------------------------------
__global__ void fill_kernel(float4* __restrict__ out4, int n4, int stride) {
    int t = blockIdx.x * blockDim.x + threadIdx.x;
    if (t < NTIER * NC) ((int*)g_cnt)[t] = 0;
    const int ca4 = CA / 4;
    const float4 zero = make_float4(0.f, 0.f, 0.f, 0.f);
    const float4 neg1 = make_float4(-1.f, -1.f, -1.f, -1.f);
    int i0 = t, i1 = t + stride, i2 = t + 2 * stride, i3 = t + 3 * stride;
    if (i0 < n4) __stcs(&out4[i0], (i0 >= ca4 && i0 < 2 * ca4) ? neg1 : zero);
    if (i1 < n4) __stcs(&out4[i1], (i1 >= ca4 && i1 < 2 * ca4) ? neg1 : zero);
    if (i2 < n4) __stcs(&out4[i2], (i2 >= ca4 && i2 < 2 * ca4) ? neg1 : zero);
    if (i3 < n4) __stcs(&out4[i3], (i3 >= ca4 && i3 < 2 * ca4) ? neg1 : zero);
}

// ---------------------------------------------------------------------------
// Tiny scatter: overwrite kept entries in the filled output
// ---------------------------------------------------------------------------
__global__ void scatter_kernel(float* __restrict__ out) {
    int c = blockIdx.x;
    int kc = g_kcnt[c];
    for (int t = threadIdx.x; t < kc; t += blockDim.x) {
        int i = g_kidg[c][t];
        out[c * AN + i] = g_kscg[c][t];
        out[CA + c * AN + i] = (float)c;
        ((float4*)(out + 2 * CA))[c * AN + i] = g_kboxg[c][t];
        out[6 * CA + c * AN + i] = 1.0f;
    }
}

// ---------------------------------------------------------------------------
// Per-class NMS, 1024 threads/block, 64-candidate batches with uint64 masks.
// ---------------------------------------------------------------------------
__global__ __launch_bounds__(NT) void nms_kernel(const float* __restrict__ cls) {
    const int c = blockIdx.x;
    const int tid = threadIdx.x;
    const int lane = tid & 31, wid = tid >> 5;

    __shared__ unsigned long long skey[CAP];        // 16KB (fallback: supp bitmap)
    __shared__ unsigned long long cmask64[NB];      // conflict rows (symmetric)
    __shared__ float4 bbox[NB];
    __shared__ float bar_[NB], bsc[NB];
    __shared__ int bidx[NB];
    __shared__ float4 kbox[MAXKEEP];
    __shared__ float kar[MAXKEEP], ksc[MAXKEEP];
    __shared__ int kid[MAXKEEP];
    __shared__ unsigned confParts[32];
    __shared__ unsigned long long alive64_s, km64_s;
    __shared__ unsigned long long red32[32];        // fallback warp-reduce
    __shared__ int kcount;

    unsigned* cmW = (unsigned*)cmask64;
    unsigned* kmW = (unsigned*)&km64_s;

    if (tid == 0) kcount = 0;
    __syncthreads();

    bool ok = true;
    for (int tier = 0; tier < NTIER; tier++) {
        if (kcount >= MAXKEEP) break;
        int n = g_cnt[tier][c];
        if (n > CAP) { ok = false; break; }
        if (n == 0) continue;

        // ---- load + pad + bitonic sort descending ----
        for (int i = tid; i < n; i += NT) skey[i] = g_cand[tier][c][i];
        int m = 1;
        while (m < n) m <<= 1;
        for (int i = n + tid; i < m; i += NT) skey[i] = 0ULL;
        __syncthreads();
        for (int k = 2; k <= m; k <<= 1) {
            for (int j = k >> 1; j > 0; j >>= 1) {
                for (int i = tid; i < m; i += NT) {
                    int ixj = i ^ j;
                    if (ixj > i) {
                        bool desc = ((i & k) == 0);
                        unsigned long long A = skey[i], B2 = skey[ixj];
                        if (desc ? (A < B2) : (A > B2)) { skey[i] = B2; skey[ixj] = A; }
                    }
                }
                __syncthreads();
            }
        }

        // ---- batched walk, NB=64 ----
        for (int base = 0; base < n; base += NB) {
            if (kcount >= MAXKEEP) break;
            int nb = min(NB, n - base);

            if (tid < nb) {
                unsigned long long key = skey[base + tid];
                float s = __uint_as_float((unsigned)(key >> 32));
                int idx = (int)(0xFFFFFFFFu - (unsigned)key);
                float4 bb;
                bb.x = g_boxes[idx * 4 + 0];
                bb.y = g_boxes[idx * 4 + 1];
                bb.z = g_boxes[idx * 4 + 2];
                bb.w = g_boxes[idx * 4 + 3];
                bbox[tid] = bb;
                bar_[tid] = g_area[idx];
                bsc[tid] = s;
                bidx[tid] = idx;
            }
            __syncthreads();

            int i = tid & 63;
            int g = tid >> 6;  // 0..15
            bool have = i < nb;
            float4 mb = make_float4(0, 0, 0, 0);
            float ma = 0;
            if (have) { mb = bbox[i]; ma = bar_[i]; }

            // phase 1a: conflict vs kept list, 16-way split per candidate
            int kc = kcount;
            bool cfk = false;
            if (have) {
                for (int j = g; j < kc; j += 16) {
                    float4 kb = kbox[j];
                    float ix1 = fmaxf(kb.x, mb.x), iy1 = fmaxf(kb.y, mb.y);
                    float ix2 = fminf(kb.z, mb.z), iy2 = fminf(kb.w, mb.w);
                    float inter = fmaxf(ix2 - ix1, 0.0f) * fmaxf(iy2 - iy1, 0.0f);
                    if (inter > 0.0f) {
                        float iou = inter / ((kar[j] + ma) - inter);
                        if (iou > 0.5f) { cfk = true; break; }
                    }
                }
            }
            unsigned cb = __ballot_sync(FULLW, cfk);
            if (lane == 0) confParts[wid] = cb;
            __syncthreads();
            if (tid == 0) {
                unsigned lo = 0, hi2 = 0;
                #pragma unroll
                for (int w = 0; w < 32; w += 2) { lo |= confParts[w]; hi2 |= confParts[w + 1]; }
                unsigned long long conf = ((unsigned long long)hi2 << 32) | lo;
                unsigned long long hv = (nb >= 64) ? ~0ULL : ((1ULL << nb) - 1ULL);
                alive64_s = hv & ~conf;
            }
            __syncthreads();
            unsigned long long alive64 = alive64_s;

            // phase 1b: conflict matrix, 16 columns per ballot round (<=4 rounds)
            for (int jb = 0; jb < nb; jb += 16) {
                int j = jb + g;
                bool cf = false;
                if (have && j < nb && i != j) {
                    float4 jb4 = bbox[j];
                    float ja = bar_[j];
                    float ix1 = fmaxf(jb4.x, mb.x), iy1 = fmaxf(jb4.y, mb.y);
                    float ix2 = fminf(jb4.z, mb.z), iy2 = fminf(jb4.w, mb.w);
                    float inter = fmaxf(ix2 - ix1, 0.0f) * fmaxf(iy2 - iy1, 0.0f);
                    if (inter > 0.0f) {
                        float iou = inter / ((ja + ma) - inter);
                        cf = iou > 0.5f;
                    }
                }
                unsigned bits = __ballot_sync(FULLW, cf);
                if (lane == 0 && j < nb) cmW[2 * j + (wid & 1)] = bits;
            }
            __syncthreads();

            // classify trivial/deferred (threads 0..63 = warps 0,1)
            {
                bool trivial = false, deferred = false;
                if (tid < 64) {
                    if ((alive64 >> tid) & 1ULL) {
                        unsigned long long below = (1ULL << tid) - 1ULL;
                        unsigned long long conf = cmask64[tid] & alive64 & below;
                        trivial = (conf == 0ULL);
                        deferred = !trivial;
                    }
                }
                unsigned tb = __ballot_sync(FULLW, trivial);
                unsigned db = __ballot_sync(FULLW, deferred);
                if (lane == 0 && wid < 2) kmW[wid] = tb;
                if (lane == 1 && wid < 2) red32[wid] = db;  // stash deferred halves
            }
            __syncthreads();

            // thread 0: resolve deferred serially with 64-bit masks, truncate
            if (tid == 0) {
                unsigned long long kw = km64_s;
                unsigned long long dbits = ((unsigned long long)(unsigned)red32[1] << 32) |
                                           (unsigned)red32[0];
                while (dbits) {
                    int q = __ffsll((long long)dbits) - 1;
                    dbits &= dbits - 1ULL;
                    unsigned long long below = (1ULL << q) - 1ULL;
                    if ((cmask64[q] & kw & below) == 0ULL) kw |= (1ULL << q);
                }
                int rem = MAXKEEP - kcount;
                int p = __popcll(kw);
                while (p > rem) {
                    kw &= ~(0x8000000000000000ULL >> __clzll((long long)kw));
                    p--;
                }
                km64_s = kw;
            }
            __syncthreads();

            unsigned long long kw = km64_s;
            int kc0 = kcount;
            if (tid < 64 && ((kw >> tid) & 1ULL)) {
                int pos = kc0 + __popcll(kw & ((1ULL << tid) - 1ULL));
                kbox[pos] = bbox[tid];
                kar[pos] = bar_[tid];
                ksc[pos] = bsc[tid];
                kid[pos] = bidx[tid];
            }
            __syncthreads();
            if (tid == 0) kcount = kc0 + __popcll(kw);
            __syncthreads();
        }
    }
    __syncthreads();

    // ---- Exact fallback (never triggered for this data) ----
    if (!ok || kcount < MAXKEEP) {
        unsigned* supp = (unsigned*)skey;  // 9.6KB of 16KB
        const int NW = (AN + 31) / 32;
        for (int w2 = tid; w2 < NW; w2 += NT) supp[w2] = 0u;
        if (tid == 0) kcount = 0;
        __syncthreads();
        for (int it = 0; it < MAXKEEP; it++) {
            unsigned long long best = 0ULL;
            for (int i = tid; i < AN; i += NT) {
                if (!((supp[i >> 5] >> (i & 31)) & 1u)) {
                    float s = cls[i * NC + c];
                    if (s > 0.1f) {
                        unsigned long long k =
                            ((unsigned long long)__float_as_uint(s) << 32) |
                            (unsigned long long)(0xFFFFFFFFu - (unsigned)i);
                        if (k > best) best = k;
                    }
                }
            }
            #pragma unroll
            for (int off = 16; off > 0; off >>= 1) {
                unsigned long long o = __shfl_down_sync(FULLW, best, off);
                if (o > best) best = o;
            }
            if (lane == 0) red32[wid] = best;
            __syncthreads();
            if (tid == 0) {
                unsigned long long b2 = red32[0];
                for (int w = 1; w < 32; w++)
                    if (red32[w] > b2) b2 = red32[w];
                red32[0] = b2;
            }
            __syncthreads();
            unsigned long long bk = red32[0];
            __syncthreads();
            if (bk == 0ULL) break;
            int bi = (int)(0xFFFFFFFFu - (unsigned)bk);
            float s = __uint_as_float((unsigned)(bk >> 32));
            float zx1 = g_boxes[bi * 4 + 0], zy1 = g_boxes[bi * 4 + 1];
            float zx2 = g_boxes[bi * 4 + 2], zy2 = g_boxes[bi * 4 + 3];
            float za = g_area[bi];
            if (tid == 0) {
                int kc2 = kcount;
                kbox[kc2] = make_float4(zx1, zy1, zx2, zy2);
                kar[kc2] = za; ksc[kc2] = s; kid[kc2] = bi;
                kcount = kc2 + 1;
            }
            for (int i = tid; i < AN; i += NT) {
                float ix1 = fmaxf(zx1, g_boxes[i * 4 + 0]);
                float iy1 = fmaxf(zy1, g_boxes[i * 4 + 1]);
                float ix2 = fminf(zx2, g_boxes[i * 4 + 2]);
                float iy2 = fminf(zy2, g_boxes[i * 4 + 3]);
                float inter = fmaxf(ix2 - ix1, 0.0f) * fmaxf(iy2 - iy1, 0.0f);
                float iou = inter / ((za + g_area[i]) - inter);
                if (iou > 0.5f || i == bi) atomicOr(&supp[i >> 5], 1u << (i & 31));
            }
            __syncthreads();
        }
        __syncthreads();
    }

    // ---- write compact results to device globals ----
    int kc = kcount;
    if (tid == 0) g_kcnt[c] = kc;
    for (int t = tid; t < kc; t += NT) {
        g_kboxg[c][t] = kbox[t];
        g_kscg[c][t] = ksc[t];
        g_kidg[c][t] = kid[t];
    }
}

// ---------------------------------------------------------------------------
extern "C" void kernel_launch(void* const* d_in, const int* in_sizes, int n_in,
                              void* d_out, int out_size) {
    const float* classification = (const float*)d_in[0];  // [1, A, C]
    const float* regression = (const float*)d_in[1];      // [1, A, 4]
    const float* anchors = (const float*)d_in[2];         // [A, 4]
    float* out = (float*)d_out;

    int n4 = out_size / 4;
    int threads_needed = (n4 + 3) / 4;
    int fill_blocks = (threads_needed + 255) / 256;
    int stride = fill_blocks * 256;
    // fill also resets candidate counters -> must precede prep
    fill_kernel<<<fill_blocks, 256>>>((float4*)out, n4, stride);

    int prep_blocks = (CA / 4 + 255) / 256;
    prep_kernel<<<prep_blocks, 256>>>(classification, anchors, regression);

    nms_kernel<<<NC, NT>>>(classification);
    scatter_kernel<<<NC, 256>>>(out);
}

// round 9
// speedup vs baseline: 1.0265x; 1.0265x over previous
#include <cuda_runtime.h>

#define AN 76725
#define NC 80
#define CA (AN * NC)
#define CAP 2048
#define NTIER 3
#define MAXKEEP 200
#define IMGF 640.0f
#define T_A 0.9963f
#define T_B 0.99f
#define T_C 0.97f
#define NT 1024
#define NB 64
#define FILLB 148
#define FULLW 0xFFFFFFFFu

// Scratch (device globals: no allocation allowed; zero-initialized at load,
// g_cnt is re-zeroed by scatter_kernel at the end of every call)
__device__ float g_boxes[AN * 4];  // decoded boxes
__device__ float g_area[AN];
__device__ unsigned long long g_cand[NTIER][NC][CAP];  // per-tier per-class keys
__device__ int g_cnt[NTIER][NC];
// compact per-class NMS results
__device__ int g_kcnt[NC];
__device__ float4 g_kboxg[NC][MAXKEEP];
__device__ float g_kscg[NC][MAXKEEP];
__device__ int g_kidg[NC][MAXKEEP];

// ---------------------------------------------------------------------------
// Fused prep: candidate gather (float4 over [A,C]) + box decode.
// g_cnt is zero on entry (initial load state / reset by previous scatter).
// ---------------------------------------------------------------------------
__global__ void prep_kernel(const float* __restrict__ cls,
                            const float* __restrict__ anchors,
                            const float* __restrict__ reg) {
    int t = blockIdx.x * blockDim.x + threadIdx.x;

    // decode duty for the first AN threads
    if (t < AN) {
        int i = t;
        float a0 = anchors[i * 4 + 0], a1 = anchors[i * 4 + 1];
        float a2 = anchors[i * 4 + 2], a3 = anchors[i * 4 + 3];
        float r0 = reg[i * 4 + 0], r1 = reg[i * 4 + 1];
        float r2 = reg[i * 4 + 2], r3 = reg[i * 4 + 3];
        float aw = a2 - a0, ah = a3 - a1;
        float ax = a0 + 0.5f * aw, ay = a1 + 0.5f * ah;
        float cx = ax + r0 * 0.1f * aw;
        float cy = ay + r1 * 0.1f * ah;
        float w = aw * expf(r2 * 0.2f);
        float h = ah * expf(r3 * 0.2f);
        float x1 = fminf(fmaxf(cx - 0.5f * w, 0.0f), IMGF);
        float y1 = fminf(fmaxf(cy - 0.5f * h, 0.0f), IMGF);
        float x2 = fminf(fmaxf(cx + 0.5f * w, 0.0f), IMGF);
        float y2 = fminf(fmaxf(cy + 0.5f * h, 0.0f), IMGF);
        g_boxes[i * 4 + 0] = x1;
        g_boxes[i * 4 + 1] = y1;
        g_boxes[i * 4 + 2] = x2;
        g_boxes[i * 4 + 3] = y2;
        g_area[i] = (x2 - x1) * (y2 - y1);
    }

    // gather duty: 4 consecutive scores per thread
    if (t < CA / 4) {
        float4 v = ((const float4*)cls)[t];
        float sv[4] = {v.x, v.y, v.z, v.w};
        #pragma unroll
        for (int k = 0; k < 4; k++) {
            float s = sv[k];
            if (s > T_C) {
                int f = t * 4 + k;
                int c = f % NC;
                int a = f / NC;
                int tier = (s > T_A) ? 0 : ((s > T_B) ? 1 : 2);
                int p = atomicAdd(&g_cnt[tier][c], 1);
                if (p < CAP)
                    g_cand[tier][c][p] =
                        ((unsigned long long)__float_as_uint(s) << 32) |
                        (unsigned long long)(0xFFFFFFFFu - (unsigned)a);
            }
        }
    }
}

// ---------------------------------------------------------------------------
// Tiny scatter: overwrite kept entries in the filled output.
// Also resets g_cnt for the NEXT call (deterministic: every call starts
// from the same zeroed counter state).
// ---------------------------------------------------------------------------
__global__ void scatter_kernel(float* __restrict__ out) {
    int c = blockIdx.x;
    if (c == 0 && threadIdx.x < NTIER * NC) ((int*)g_cnt)[threadIdx.x] = 0;
    int kc = g_kcnt[c];
    for (int t = threadIdx.x; t < kc; t += blockDim.x) {
        int i = g_kidg[c][t];
        out[c * AN + i] = g_kscg[c][t];
        out[CA + c * AN + i] = (float)c;
        ((float4*)(out + 2 * CA))[c * AN + i] = g_kboxg[c][t];
        out[6 * CA + c * AN + i] = 1.0f;
    }
}

// ---------------------------------------------------------------------------
// Fused NMS + output fill. Blocks [0, NC): per-class NMS (1024 threads,
// 64-candidate batches, uint64 masks). Blocks [NC, NC+FILLB): grid-stride
// default fill of the output (zeros everywhere, -1 in the labels region).
// The fill is DRAM-bound and runs on the SMs the NMS blocks don't occupy,
// hiding the entire NMS latency inside the fill time.
// ---------------------------------------------------------------------------
__global__ __launch_bounds__(NT) void fused_kernel(const float* __restrict__ cls,
                                                   float4* __restrict__ out4,
                                                   int n4) {
    // ---------------- fill path ----------------
    if (blockIdx.x >= NC) {
        int fb = blockIdx.x - NC;
        const int ca4 = CA / 4;
        int stride = FILLB * NT;
        for (int i = fb * NT + threadIdx.x; i < n4; i += stride) {
            float v = (i >= ca4 && i < 2 * ca4) ? -1.0f : 0.0f;
            out4[i] = make_float4(v, v, v, v);
        }
        return;
    }

    // ---------------- NMS path ----------------
    const int c = blockIdx.x;
    const int tid = threadIdx.x;
    const int lane = tid & 31, wid = tid >> 5;

    __shared__ unsigned long long skey[CAP];        // 16KB (fallback: supp bitmap)
    __shared__ unsigned long long cmask64[NB];      // conflict rows (symmetric)
    __shared__ float4 bbox[NB];
    __shared__ float bar_[NB], bsc[NB];
    __shared__ int bidx[NB];
    __shared__ float4 kbox[MAXKEEP];
    __shared__ float kar[MAXKEEP], ksc[MAXKEEP];
    __shared__ int kid[MAXKEEP];
    __shared__ unsigned confParts[32];
    __shared__ unsigned long long alive64_s, km64_s;
    __shared__ unsigned long long red32[32];        // fallback warp-reduce
    __shared__ int kcount;

    unsigned* cmW = (unsigned*)cmask64;
    unsigned* kmW = (unsigned*)&km64_s;

    if (tid == 0) kcount = 0;
    __syncthreads();

    bool ok = true;
    for (int tier = 0; tier < NTIER; tier++) {
        if (kcount >= MAXKEEP) break;
        int n = g_cnt[tier][c];
        if (n > CAP) { ok = false; break; }
        if (n == 0) continue;

        // ---- load + pad + bitonic sort descending ----
        for (int i = tid; i < n; i += NT) skey[i] = g_cand[tier][c][i];
        int m = 1;
        while (m < n) m <<= 1;
        for (int i = n + tid; i < m; i += NT) skey[i] = 0ULL;
        __syncthreads();
        for (int k = 2; k <= m; k <<= 1) {
            for (int j = k >> 1; j > 0; j >>= 1) {
                for (int i = tid; i < m; i += NT) {
                    int ixj = i ^ j;
                    if (ixj > i) {
                        bool desc = ((i & k) == 0);
                        unsigned long long A = skey[i], B2 = skey[ixj];
                        if (desc ? (A < B2) : (A > B2)) { skey[i] = B2; skey[ixj] = A; }
                    }
                }
                __syncthreads();
            }
        }

        // ---- batched walk, NB=64 ----
        for (int base = 0; base < n; base += NB) {
            if (kcount >= MAXKEEP) break;
            int nb = min(NB, n - base);

            if (tid < nb) {
                unsigned long long key = skey[base + tid];
                float s = __uint_as_float((unsigned)(key >> 32));
                int idx = (int)(0xFFFFFFFFu - (unsigned)key);
                float4 bb;
                bb.x = g_boxes[idx * 4 + 0];
                bb.y = g_boxes[idx * 4 + 1];
                bb.z = g_boxes[idx * 4 + 2];
                bb.w = g_boxes[idx * 4 + 3];
                bbox[tid] = bb;
                bar_[tid] = g_area[idx];
                bsc[tid] = s;
                bidx[tid] = idx;
            }
            __syncthreads();

            int i = tid & 63;
            int g = tid >> 6;  // 0..15
            bool have = i < nb;
            float4 mb = make_float4(0, 0, 0, 0);
            float ma = 0;
            if (have) { mb = bbox[i]; ma = bar_[i]; }

            // phase 1a: conflict vs kept list, 16-way split per candidate
            int kc = kcount;
            bool cfk = false;
            if (have) {
                for (int j = g; j < kc; j += 16) {
                    float4 kb = kbox[j];
                    float ix1 = fmaxf(kb.x, mb.x), iy1 = fmaxf(kb.y, mb.y);
                    float ix2 = fminf(kb.z, mb.z), iy2 = fminf(kb.w, mb.w);
                    float inter = fmaxf(ix2 - ix1, 0.0f) * fmaxf(iy2 - iy1, 0.0f);
                    if (inter > 0.0f) {
                        float iou = inter / ((kar[j] + ma) - inter);
                        if (iou > 0.5f) { cfk = true; break; }
                    }
                }
            }
            unsigned cb = __ballot_sync(FULLW, cfk);
            if (lane == 0) confParts[wid] = cb;
            __syncthreads();
            if (tid == 0) {
                unsigned lo = 0, hi2 = 0;
                #pragma unroll
                for (int w = 0; w < 32; w += 2) { lo |= confParts[w]; hi2 |= confParts[w + 1]; }
                unsigned long long conf = ((unsigned long long)hi2 << 32) | lo;
                unsigned long long hv = (nb >= 64) ? ~0ULL : ((1ULL << nb) - 1ULL);
                alive64_s = hv & ~conf;
            }
            __syncthreads();
            unsigned long long alive64 = alive64_s;

            // phase 1b: conflict matrix, 16 columns per ballot round (<=4 rounds)
            for (int jb = 0; jb < nb; jb += 16) {
                int j = jb + g;
                bool cf = false;
                if (have && j < nb && i != j) {
                    float4 jb4 = bbox[j];
                    float ja = bar_[j];
                    float ix1 = fmaxf(jb4.x, mb.x), iy1 = fmaxf(jb4.y, mb.y);
                    float ix2 = fminf(jb4.z, mb.z), iy2 = fminf(jb4.w, mb.w);
                    float inter = fmaxf(ix2 - ix1, 0.0f) * fmaxf(iy2 - iy1, 0.0f);
                    if (inter > 0.0f) {
                        float iou = inter / ((ja + ma) - inter);
                        cf = iou > 0.5f;
                    }
                }
                unsigned bits = __ballot_sync(FULLW, cf);
                if (lane == 0 && j < nb) cmW[2 * j + (wid & 1)] = bits;
            }
            __syncthreads();

            // classify trivial/deferred (threads 0..63 = warps 0,1)
            {
                bool trivial = false, deferred = false;
                if (tid < 64) {
                    if ((alive64 >> tid) & 1ULL) {
                        unsigned long long below = (1ULL << tid) - 1ULL;
                        unsigned long long conf = cmask64[tid] & alive64 & below;
                        trivial = (conf == 0ULL);
                        deferred = !trivial;
                    }
                }
                unsigned tb = __ballot_sync(FULLW, trivial);
                unsigned db = __ballot_sync(FULLW, deferred);
                if (lane == 0 && wid < 2) kmW[wid] = tb;
                if (lane == 1 && wid < 2) red32[wid] = db;  // stash deferred halves
            }
            __syncthreads();

            // thread 0: resolve deferred serially with 64-bit masks, truncate
            if (tid == 0) {
                unsigned long long kw = km64_s;
                unsigned long long dbits = ((unsigned long long)(unsigned)red32[1] << 32) |
                                           (unsigned)red32[0];
                while (dbits) {
                    int q = __ffsll((long long)dbits) - 1;
                    dbits &= dbits - 1ULL;
                    unsigned long long below = (1ULL << q) - 1ULL;
                    if ((cmask64[q] & kw & below) == 0ULL) kw |= (1ULL << q);
                }
                int rem = MAXKEEP - kcount;
                int p = __popcll(kw);
                while (p > rem) {
                    kw &= ~(0x8000000000000000ULL >> __clzll((long long)kw));
                    p--;
                }
                km64_s = kw;
            }
            __syncthreads();

            unsigned long long kw = km64_s;
            int kc0 = kcount;
            if (tid < 64 && ((kw >> tid) & 1ULL)) {
                int pos = kc0 + __popcll(kw & ((1ULL << tid) - 1ULL));
                kbox[pos] = bbox[tid];
                kar[pos] = bar_[tid];
                ksc[pos] = bsc[tid];
                kid[pos] = bidx[tid];
            }
            __syncthreads();
            if (tid == 0) kcount = kc0 + __popcll(kw);
            __syncthreads();
        }
    }
    __syncthreads();

    // ---- Exact fallback (never triggered for this data) ----
    if (!ok || kcount < MAXKEEP) {
        unsigned* supp = (unsigned*)skey;  // 9.6KB of 16KB
        const int NW = (AN + 31) / 32;
        for (int w2 = tid; w2 < NW; w2 += NT) supp[w2] = 0u;
        if (tid == 0) kcount = 0;
        __syncthreads();
        for (int it = 0; it < MAXKEEP; it++) {
            unsigned long long best = 0ULL;
            for (int i = tid; i < AN; i += NT) {
                if (!((supp[i >> 5] >> (i & 31)) & 1u)) {
                    float s = cls[i * NC + c];
                    if (s > 0.1f) {
                        unsigned long long k =
                            ((unsigned long long)__float_as_uint(s) << 32) |
                            (unsigned long long)(0xFFFFFFFFu - (unsigned)i);
                        if (k > best) best = k;
                    }
                }
            }
            #pragma unroll
            for (int off = 16; off > 0; off >>= 1) {
                unsigned long long o = __shfl_down_sync(FULLW, best, off);
                if (o > best) best = o;
            }
            if (lane == 0) red32[wid] = best;
            __syncthreads();
            if (tid == 0) {
                unsigned long long b2 = red32[0];
                for (int w = 1; w < 32; w++)
                    if (red32[w] > b2) b2 = red32[w];
                red32[0] = b2;
            }
            __syncthreads();
            unsigned long long bk = red32[0];
            __syncthreads();
            if (bk == 0ULL) break;
            int bi = (int)(0xFFFFFFFFu - (unsigned)bk);
            float s = __uint_as_float((unsigned)(bk >> 32));
            float zx1 = g_boxes[bi * 4 + 0], zy1 = g_boxes[bi * 4 + 1];
            float zx2 = g_boxes[bi * 4 + 2], zy2 = g_boxes[bi * 4 + 3];
            float za = g_area[bi];
            if (tid == 0) {
                int kc2 = kcount;
                kbox[kc2] = make_float4(zx1, zy1, zx2, zy2);
                kar[kc2] = za; ksc[kc2] = s; kid[kc2] = bi;
                kcount = kc2 + 1;
            }
            for (int i = tid; i < AN; i += NT) {
                float ix1 = fmaxf(zx1, g_boxes[i * 4 + 0]);
                float iy1 = fmaxf(zy1, g_boxes[i * 4 + 1]);
                float ix2 = fminf(zx2, g_boxes[i * 4 + 2]);
                float iy2 = fminf(zy2, g_boxes[i * 4 + 3]);
                float inter = fmaxf(ix2 - ix1, 0.0f) * fmaxf(iy2 - iy1, 0.0f);
                float iou = inter / ((za + g_area[i]) - inter);
                if (iou > 0.5f || i == bi) atomicOr(&supp[i >> 5], 1u << (i & 31));
            }
            __syncthreads();
        }
        __syncthreads();
    }

    // ---- write compact results to device globals ----
    int kc = kcount;
    if (tid == 0) g_kcnt[c] = kc;
    for (int t = tid; t < kc; t += NT) {
        g_kboxg[c][t] = kbox[t];
        g_kscg[c][t] = ksc[t];
        g_kidg[c][t] = kid[t];
    }
}

// ---------------------------------------------------------------------------
extern "C" void kernel_launch(void* const* d_in, const int* in_sizes, int n_in,
                              void* d_out, int out_size) {
    const float* classification = (const float*)d_in[0];  // [1, A, C]
    const float* regression = (const float*)d_in[1];      // [1, A, 4]
    const float* anchors = (const float*)d_in[2];         // [A, 4]
    float* out = (float*)d_out;

    int prep_blocks = (CA / 4 + 255) / 256;
    prep_kernel<<<prep_blocks, 256>>>(classification, anchors, regression);

    int n4 = out_size / 4;
    fused_kernel<<<NC + FILLB, NT>>>(classification, (float4*)out, n4);

    scatter_kernel<<<NC, 256>>>(out);  // also resets g_cnt for the next call
}

// round 11
// speedup vs baseline: 1.5658x; 1.5253x over previous
#include <cuda_runtime.h>

#define AN 76725
#define NC 80
#define CA (AN * NC)
#define NTIER 3
#define NSUB 32
#define SUBCAP 128
#define TIERCAP (NSUB * SUBCAP)
#define SKEYN 2048
#define MAXKEEP 200
#define IMGF 640.0f
#define T_A 0.9963f
#define T_B 0.99f
#define T_C 0.97f
#define NT 1024
#define NB 64
#define FILLB 148
#define FULLW 0xFFFFFFFFu

// Scratch (device globals: no allocation allowed; zero-initialized at load,
// g_cntp is re-zeroed by scatter_kernel at the end of every call)
__device__ float g_boxes[AN * 4];  // decoded boxes
__device__ float g_area[AN];
__device__ unsigned long long g_cand[NTIER][NC][TIERCAP];  // sub-sliced candidate keys
__device__ int g_cntp[NSUB][NTIER][NC];                    // privatized counters
// compact per-class NMS results
__device__ int g_kcnt[NC];
__device__ float4 g_kboxg[NC][MAXKEEP];
__device__ float g_kscg[NC][MAXKEEP];
__device__ int g_kidg[NC][MAXKEEP];

// ---------------------------------------------------------------------------
// Fused prep: candidate gather (4x float4 per thread) + box decode.
// Counters are privatized 32 ways (per block/warp hash) to kill atomic
// contention; g_cntp is zero on entry (load state / reset by prev scatter).
// ---------------------------------------------------------------------------
__global__ void prep_kernel(const float* __restrict__ cls,
                            const float* __restrict__ anchors,
                            const float* __restrict__ reg) {
    int t = blockIdx.x * blockDim.x + threadIdx.x;
    int stride = gridDim.x * blockDim.x;
    int sub = (blockIdx.x * 8 + (threadIdx.x >> 5)) & (NSUB - 1);

    // decode duty for the first AN threads
    if (t < AN) {
        int i = t;
        float a0 = anchors[i * 4 + 0], a1 = anchors[i * 4 + 1];
        float a2 = anchors[i * 4 + 2], a3 = anchors[i * 4 + 3];
        float r0 = reg[i * 4 + 0], r1 = reg[i * 4 + 1];
        float r2 = reg[i * 4 + 2], r3 = reg[i * 4 + 3];
        float aw = a2 - a0, ah = a3 - a1;
        float ax = a0 + 0.5f * aw, ay = a1 + 0.5f * ah;
        float cx = ax + r0 * 0.1f * aw;
        float cy = ay + r1 * 0.1f * ah;
        float w = aw * expf(r2 * 0.2f);
        float h = ah * expf(r3 * 0.2f);
        float x1 = fminf(fmaxf(cx - 0.5f * w, 0.0f), IMGF);
        float y1 = fminf(fmaxf(cy - 0.5f * h, 0.0f), IMGF);
        float x2 = fminf(fmaxf(cx + 0.5f * w, 0.0f), IMGF);
        float y2 = fminf(fmaxf(cy + 0.5f * h, 0.0f), IMGF);
        g_boxes[i * 4 + 0] = x1;
        g_boxes[i * 4 + 1] = y1;
        g_boxes[i * 4 + 2] = x2;
        g_boxes[i * 4 + 3] = y2;
        g_area[i] = (x2 - x1) * (y2 - y1);
    }

    // gather duty: 4 independent float4 loads (MLP), coalesced per iteration
    #pragma unroll
    for (int jj = 0; jj < 4; jj++) {
        int q = t + jj * stride;
        if (q < CA / 4) {
            float4 v = ((const float4*)cls)[q];
            float sv[4] = {v.x, v.y, v.z, v.w};
            #pragma unroll
            for (int k = 0; k < 4; k++) {
                float s = sv[k];
                if (s > T_C) {
                    int f = q * 4 + k;
                    int c = f % NC;
                    int a = f / NC;
                    int tier = (s > T_A) ? 0 : ((s > T_B) ? 1 : 2);
                    int p = atomicAdd(&g_cntp[sub][tier][c], 1);
                    if (p < SUBCAP)
                        g_cand[tier][c][sub * SUBCAP + p] =
                            ((unsigned long long)__float_as_uint(s) << 32) |
                            (unsigned long long)(0xFFFFFFFFu - (unsigned)a);
                }
            }
        }
    }
}

// ---------------------------------------------------------------------------
// Tiny scatter: overwrite kept entries in the filled output.
// Also resets g_cntp for the NEXT call (deterministic zeroed start state).
// ---------------------------------------------------------------------------
__global__ void scatter_kernel(float* __restrict__ out) {
    int c = blockIdx.x;
    int flat = c * blockDim.x + threadIdx.x;
    if (flat < NSUB * NTIER * NC) ((int*)g_cntp)[flat] = 0;
    int kc = g_kcnt[c];
    for (int t = threadIdx.x; t < kc; t += blockDim.x) {
        int i = g_kidg[c][t];
        out[c * AN + i] = g_kscg[c][t];
        out[CA + c * AN + i] = (float)c;
        ((float4*)(out + 2 * CA))[c * AN + i] = g_kboxg[c][t];
        out[6 * CA + c * AN + i] = 1.0f;
    }
}

// ---------------------------------------------------------------------------
// Fused NMS + output fill. Blocks [0, NC): per-class NMS. Blocks
// [NC, NC+FILLB): grid-stride default fill (zeros; -1 in labels region).
// ---------------------------------------------------------------------------
__global__ __launch_bounds__(NT) void fused_kernel(const float* __restrict__ cls,
                                                   float4* __restrict__ out4,
                                                   int n4) {
    // ---------------- fill path ----------------
    if (blockIdx.x >= NC) {
        int fb = blockIdx.x - NC;
        const int ca4 = CA / 4;
        int stride = FILLB * NT;
        for (int i = fb * NT + threadIdx.x; i < n4; i += stride) {
            float v = (i >= ca4 && i < 2 * ca4) ? -1.0f : 0.0f;
            out4[i] = make_float4(v, v, v, v);
        }
        return;
    }

    // ---------------- NMS path ----------------
    const int c = blockIdx.x;
    const int tid = threadIdx.x;
    const int lane = tid & 31, wid = tid >> 5;

    __shared__ unsigned long long skey[SKEYN];      // 16KB (fallback: supp bitmap)
    __shared__ unsigned long long cmask64[NB];      // conflict rows (symmetric)
    __shared__ float4 bbox[NB];
    __shared__ float bar_[NB], bsc[NB];
    __shared__ int bidx[NB];
    __shared__ float4 kbox[MAXKEEP];
    __shared__ float kar[MAXKEEP], ksc[MAXKEEP];
    __shared__ int kid[MAXKEEP];
    __shared__ unsigned confParts[32];
    __shared__ unsigned long long alive64_s, km64_s;
    __shared__ unsigned long long red32[32];        // fallback warp-reduce
    __shared__ int kcount;

    unsigned* cmW = (unsigned*)cmask64;
    unsigned* kmW = (unsigned*)&km64_s;

    if (tid == 0) kcount = 0;
    __syncthreads();

    bool ok = true;
    for (int tier = 0; tier < NTIER; tier++) {
        if (kcount >= MAXKEEP) break;

        // concatenate the 32 sub-lists for this (tier, class)
        int n = 0;
        bool of = false;
        for (int s2 = 0; s2 < NSUB; s2++) {
            int cs = g_cntp[s2][tier][c];
            if (cs > SUBCAP) of = true;
            cs = min(cs, SUBCAP);
            for (int i = tid; i < cs; i += NT)
                skey[min(n + i, SKEYN - 1)] = g_cand[tier][c][s2 * SUBCAP + i];
            n += cs;
        }
        if (of || n > SKEYN) { ok = false; break; }
        if (n == 0) continue;

        // ---- pad + bitonic sort descending ----
        int m = 1;
        while (m < n) m <<= 1;
        for (int i = n + tid; i < m; i += NT) skey[i] = 0ULL;
        __syncthreads();
        for (int k = 2; k <= m; k <<= 1) {
            for (int j = k >> 1; j > 0; j >>= 1) {
                for (int i = tid; i < m; i += NT) {
                    int ixj = i ^ j;
                    if (ixj > i) {
                        bool desc = ((i & k) == 0);
                        unsigned long long A = skey[i], B2 = skey[ixj];
                        if (desc ? (A < B2) : (A > B2)) { skey[i] = B2; skey[ixj] = A; }
                    }
                }
                __syncthreads();
            }
        }

        // ---- batched walk, NB=64 ----
        for (int base = 0; base < n; base += NB) {
            if (kcount >= MAXKEEP) break;
            int nb = min(NB, n - base);

            if (tid < nb) {
                unsigned long long key = skey[base + tid];
                float s = __uint_as_float((unsigned)(key >> 32));
                int idx = (int)(0xFFFFFFFFu - (unsigned)key);
                float4 bb;
                bb.x = g_boxes[idx * 4 + 0];
                bb.y = g_boxes[idx * 4 + 1];
                bb.z = g_boxes[idx * 4 + 2];
                bb.w = g_boxes[idx * 4 + 3];
                bbox[tid] = bb;
                bar_[tid] = g_area[idx];
                bsc[tid] = s;
                bidx[tid] = idx;
            }
            __syncthreads();

            int i = tid & 63;
            int g = tid >> 6;  // 0..15
            bool have = i < nb;
            float4 mb = make_float4(0, 0, 0, 0);
            float ma = 0;
            if (have) { mb = bbox[i]; ma = bar_[i]; }

            // phase 1a: conflict vs kept list, 16-way split per candidate
            int kc = kcount;
            bool cfk = false;
            if (have) {
                for (int j = g; j < kc; j += 16) {
                    float4 kb = kbox[j];
                    float ix1 = fmaxf(kb.x, mb.x), iy1 = fmaxf(kb.y, mb.y);
                    float ix2 = fminf(kb.z, mb.z), iy2 = fminf(kb.w, mb.w);
                    float inter = fmaxf(ix2 - ix1, 0.0f) * fmaxf(iy2 - iy1, 0.0f);
                    if (inter > 0.0f) {
                        float iou = inter / ((kar[j] + ma) - inter);
                        if (iou > 0.5f) { cfk = true; break; }
                    }
                }
            }
            unsigned cb = __ballot_sync(FULLW, cfk);
            if (lane == 0) confParts[wid] = cb;
            __syncthreads();
            if (tid == 0) {
                unsigned lo = 0, hi2 = 0;
                #pragma unroll
                for (int w = 0; w < 32; w += 2) { lo |= confParts[w]; hi2 |= confParts[w + 1]; }
                unsigned long long conf = ((unsigned long long)hi2 << 32) | lo;
                unsigned long long hv = (nb >= 64) ? ~0ULL : ((1ULL << nb) - 1ULL);
                alive64_s = hv & ~conf;
            }
            __syncthreads();
            unsigned long long alive64 = alive64_s;

            // phase 1b: conflict matrix, 16 columns per ballot round (<=4 rounds)
            for (int jb = 0; jb < nb; jb += 16) {
                int j = jb + g;
                bool cf = false;
                if (have && j < nb && i != j) {
                    float4 jb4 = bbox[j];
                    float ja = bar_[j];
                    float ix1 = fmaxf(jb4.x, mb.x), iy1 = fmaxf(jb4.y, mb.y);
                    float ix2 = fminf(jb4.z, mb.z), iy2 = fminf(jb4.w, mb.w);
                    float inter = fmaxf(ix2 - ix1, 0.0f) * fmaxf(iy2 - iy1, 0.0f);
                    if (inter > 0.0f) {
                        float iou = inter / ((ja + ma) - inter);
                        cf = iou > 0.5f;
                    }
                }
                unsigned bits = __ballot_sync(FULLW, cf);
                if (lane == 0 && j < nb) cmW[2 * j + (wid & 1)] = bits;
            }
            __syncthreads();

            // classify trivial/deferred (threads 0..63 = warps 0,1)
            {
                bool trivial = false, deferred = false;
                if (tid < 64) {
                    if ((alive64 >> tid) & 1ULL) {
                        unsigned long long below = (1ULL << tid) - 1ULL;
                        unsigned long long conf = cmask64[tid] & alive64 & below;
                        trivial = (conf == 0ULL);
                        deferred = !trivial;
                    }
                }
                unsigned tb = __ballot_sync(FULLW, trivial);
                unsigned db = __ballot_sync(FULLW, deferred);
                if (lane == 0 && wid < 2) kmW[wid] = tb;
                if (lane == 1 && wid < 2) red32[wid] = db;  // stash deferred halves
            }
            __syncthreads();

            // thread 0: resolve deferred serially with 64-bit masks, truncate
            if (tid == 0) {
                unsigned long long kw = km64_s;
                unsigned long long dbits = ((unsigned long long)(unsigned)red32[1] << 32) |
                                           (unsigned)red32[0];
                while (dbits) {
                    int q = __ffsll((long long)dbits) - 1;
                    dbits &= dbits - 1ULL;
                    unsigned long long below = (1ULL << q) - 1ULL;
                    if ((cmask64[q] & kw & below) == 0ULL) kw |= (1ULL << q);
                }
                int rem = MAXKEEP - kcount;
                int p = __popcll(kw);
                while (p > rem) {
                    kw &= ~(0x8000000000000000ULL >> __clzll((long long)kw));
                    p--;
                }
                km64_s = kw;
            }
            __syncthreads();

            unsigned long long kw = km64_s;
            int kc0 = kcount;
            if (tid < 64 && ((kw >> tid) & 1ULL)) {
                int pos = kc0 + __popcll(kw & ((1ULL << tid) - 1ULL));
                kbox[pos] = bbox[tid];
                kar[pos] = bar_[tid];
                ksc[pos] = bsc[tid];
                kid[pos] = bidx[tid];
            }
            __syncthreads();
            if (tid == 0) kcount = kc0 + __popcll(kw);
            __syncthreads();
        }
    }
    __syncthreads();

    // ---- Exact fallback (never triggered for this data) ----
    if (!ok || kcount < MAXKEEP) {
        unsigned* supp = (unsigned*)skey;  // 9.6KB of 16KB
        const int NW = (AN + 31) / 32;
        for (int w2 = tid; w2 < NW; w2 += NT) supp[w2] = 0u;
        if (tid == 0) kcount = 0;
        __syncthreads();
        for (int it = 0; it < MAXKEEP; it++) {
            unsigned long long best = 0ULL;
            for (int i = tid; i < AN; i += NT) {
                if (!((supp[i >> 5] >> (i & 31)) & 1u)) {
                    float s = cls[i * NC + c];
                    if (s > 0.1f) {
                        unsigned long long k =
                            ((unsigned long long)__float_as_uint(s) << 32) |
                            (unsigned long long)(0xFFFFFFFFu - (unsigned)i);
                        if (k > best) best = k;
                    }
                }
            }
            #pragma unroll
            for (int off = 16; off > 0; off >>= 1) {
                unsigned long long o = __shfl_down_sync(FULLW, best, off);
                if (o > best) best = o;
            }
            if (lane == 0) red32[wid] = best;
            __syncthreads();
            if (tid == 0) {
                unsigned long long b2 = red32[0];
                for (int w = 1; w < 32; w++)
                    if (red32[w] > b2) b2 = red32[w];
                red32[0] = b2;
            }
            __syncthreads();
            unsigned long long bk = red32[0];
            __syncthreads();
            if (bk == 0ULL) break;
            int bi = (int)(0xFFFFFFFFu - (unsigned)bk);
            float s = __uint_as_float((unsigned)(bk >> 32));
            float zx1 = g_boxes[bi * 4 + 0], zy1 = g_boxes[bi * 4 + 1];
            float zx2 = g_boxes[bi * 4 + 2], zy2 = g_boxes[bi * 4 + 3];
            float za = g_area[bi];
            if (tid == 0) {
                int kc2 = kcount;
                kbox[kc2] = make_float4(zx1, zy1, zx2, zy2);
                kar[kc2] = za; ksc[kc2] = s; kid[kc2] = bi;
                kcount = kc2 + 1;
            }
            for (int i = tid; i < AN; i += NT) {
                float ix1 = fmaxf(zx1, g_boxes[i * 4 + 0]);
                float iy1 = fmaxf(zy1, g_boxes[i * 4 + 1]);
                float ix2 = fminf(zx2, g_boxes[i * 4 + 2]);
                float iy2 = fminf(zy2, g_boxes[i * 4 + 3]);
                float inter = fmaxf(ix2 - ix1, 0.0f) * fmaxf(iy2 - iy1, 0.0f);
                float iou = inter / ((za + g_area[i]) - inter);
                if (iou > 0.5f || i == bi) atomicOr(&supp[i >> 5], 1u << (i & 31));
            }
            __syncthreads();
        }
        __syncthreads();
    }

    // ---- write compact results to device globals ----
    int kc = kcount;
    if (tid == 0) g_kcnt[c] = kc;
    for (int t = tid; t < kc; t += NT) {
        g_kboxg[c][t] = kbox[t];
        g_kscg[c][t] = ksc[t];
        g_kidg[c][t] = kid[t];
    }
}

// ---------------------------------------------------------------------------
extern "C" void kernel_launch(void* const* d_in, const int* in_sizes, int n_in,
                              void* d_out, int out_size) {
    const float* classification = (const float*)d_in[0];  // [1, A, C]
    const float* regression = (const float*)d_in[1];      // [1, A, 4]
    const float* anchors = (const float*)d_in[2];         // [A, 4]
    float* out = (float*)d_out;

    // each thread covers 4 float4s = 16 scores
    int prep_blocks = (CA / 16 + 255) / 256;
    prep_kernel<<<prep_blocks, 256>>>(classification, anchors, regression);

    int n4 = out_size / 4;
    fused_kernel<<<NC + FILLB, NT>>>(classification, (float4*)out, n4);

    scatter_kernel<<<NC, 256>>>(out);  // also resets g_cntp for the next call
}

// round 12
// speedup vs baseline: 1.6522x; 1.0552x over previous
#include <cuda_runtime.h>

#define AN 76725
#define NC 80
#define CA (AN * NC)
#define NTIER 3
#define NTC (NTIER * NC)
#define CAP 2048
#define SKEYN 2048
#define STAGE 1024
#define PREPB 300
#define CHUNK4 ((CA / 4 + PREPB - 1) / PREPB)
#define MAXKEEP 200
#define IMGF 640.0f
#define T_A 0.9963f
#define T_B 0.99f
#define T_C 0.97f
#define NT 1024
#define NB 64
#define FILLB 148
#define FULLW 0xFFFFFFFFu

// Scratch (device globals: no allocation allowed; zero-initialized at load,
// g_cnt/g_of are re-zeroed by scatter_kernel at the end of every call)
__device__ float g_boxes[AN * 4];  // decoded boxes
__device__ float g_area[AN];
__device__ unsigned long long g_cand[NTIER][NC][CAP];  // candidate keys per tier/class
__device__ int g_cnt[NTIER][NC];                       // global list sizes
__device__ int g_of;                                   // overflow flag -> exact fallback
// compact per-class NMS results
__device__ int g_kcnt[NC];
__device__ float4 g_kboxg[NC][MAXKEEP];
__device__ float g_kscg[NC][MAXKEEP];
__device__ int g_kidg[NC][MAXKEEP];

// ---------------------------------------------------------------------------
// Fused prep: block-staged candidate gather (no per-candidate global atomics)
// + box decode. Phase A: stage candidates in shared (shared atomics only).
// Phase B: <=240 global atomicAdds per block reserve output ranges.
// Phase C: scatter staged keys to reserved global slots.
// ---------------------------------------------------------------------------
__global__ __launch_bounds__(256) void prep_kernel(const float* __restrict__ cls,
                                                   const float* __restrict__ anchors,
                                                   const float* __restrict__ reg) {
    __shared__ unsigned long long s_stage[STAGE];
    __shared__ unsigned char s_tc[STAGE];
    __shared__ int s_hist[NTC];
    __shared__ int s_cur[NTC];
    __shared__ int s_cnt;

    int tid = threadIdx.x;
    int t = blockIdx.x * 256 + tid;

    for (int i = tid; i < NTC; i += 256) s_hist[i] = 0;
    if (tid == 0) s_cnt = 0;

    // decode duty for the first AN threads (grid covers AN)
    if (t < AN) {
        int i = t;
        float a0 = anchors[i * 4 + 0], a1 = anchors[i * 4 + 1];
        float a2 = anchors[i * 4 + 2], a3 = anchors[i * 4 + 3];
        float r0 = reg[i * 4 + 0], r1 = reg[i * 4 + 1];
        float r2 = reg[i * 4 + 2], r3 = reg[i * 4 + 3];
        float aw = a2 - a0, ah = a3 - a1;
        float ax = a0 + 0.5f * aw, ay = a1 + 0.5f * ah;
        float cx = ax + r0 * 0.1f * aw;
        float cy = ay + r1 * 0.1f * ah;
        float w = aw * expf(r2 * 0.2f);
        float h = ah * expf(r3 * 0.2f);
        float x1 = fminf(fmaxf(cx - 0.5f * w, 0.0f), IMGF);
        float y1 = fminf(fmaxf(cy - 0.5f * h, 0.0f), IMGF);
        float x2 = fminf(fmaxf(cx + 0.5f * w, 0.0f), IMGF);
        float y2 = fminf(fmaxf(cy + 0.5f * h, 0.0f), IMGF);
        g_boxes[i * 4 + 0] = x1;
        g_boxes[i * 4 + 1] = y1;
        g_boxes[i * 4 + 2] = x2;
        g_boxes[i * 4 + 3] = y2;
        g_area[i] = (x2 - x1) * (y2 - y1);
    }
    __syncthreads();

    // Phase A: scan this block's chunk, stage candidates in shared
    int q0 = blockIdx.x * CHUNK4;
    int q1 = min(q0 + CHUNK4, CA / 4);
    for (int q = q0 + tid; q < q1; q += 256) {
        float4 v = ((const float4*)cls)[q];
        float sv[4] = {v.x, v.y, v.z, v.w};
        #pragma unroll
        for (int k = 0; k < 4; k++) {
            float s = sv[k];
            if (s > T_C) {
                int f = q * 4 + k;
                int c = f % NC;
                int a = f / NC;
                int tier = (s > T_A) ? 0 : ((s > T_B) ? 1 : 2);
                int tc = tier * NC + c;
                int p = atomicAdd(&s_cnt, 1);
                if (p < STAGE) {
                    s_stage[p] = ((unsigned long long)__float_as_uint(s) << 32) |
                                 (unsigned long long)(0xFFFFFFFFu - (unsigned)a);
                    s_tc[p] = (unsigned char)tc;
                    atomicAdd(&s_hist[tc], 1);
                } else {
                    g_of = 1;  // staging overflow -> exact fallback everywhere
                }
            }
        }
    }
    __syncthreads();

    // Phase B: reserve global ranges (<=240 global atomics per block)
    if (tid < NTC) {
        int cnt = s_hist[tid];
        s_cur[tid] = cnt ? atomicAdd(&((int*)g_cnt)[tid], cnt) : 0;
    }
    __syncthreads();

    // Phase C: scatter staged keys to reserved slots
    int nstaged = min(s_cnt, STAGE);
    for (int r = tid; r < nstaged; r += 256) {
        int tc = s_tc[r];
        int pos = atomicAdd(&s_cur[tc], 1);
        if (pos < CAP)
            g_cand[0][0][tc * CAP + pos] = s_stage[r];
        // pos >= CAP is detected in nms via g_cnt > SKEYN -> fallback
    }
}

// ---------------------------------------------------------------------------
// Tiny scatter: overwrite kept entries in the filled output.
// Also resets g_cnt/g_of for the NEXT call (deterministic zeroed start).
// ---------------------------------------------------------------------------
__global__ void scatter_kernel(float* __restrict__ out) {
    int c = blockIdx.x;
    if (c == 0) {
        if (threadIdx.x < NTC) ((int*)g_cnt)[threadIdx.x] = 0;
        if (threadIdx.x == NTC) g_of = 0;
    }
    int kc = g_kcnt[c];
    for (int t = threadIdx.x; t < kc; t += blockDim.x) {
        int i = g_kidg[c][t];
        out[c * AN + i] = g_kscg[c][t];
        out[CA + c * AN + i] = (float)c;
        ((float4*)(out + 2 * CA))[c * AN + i] = g_kboxg[c][t];
        out[6 * CA + c * AN + i] = 1.0f;
    }
}

// ---------------------------------------------------------------------------
// Fused NMS + output fill. Blocks [0, NC): per-class NMS. Blocks
// [NC, NC+FILLB): grid-stride default fill (zeros; -1 in labels region).
// ---------------------------------------------------------------------------
__global__ __launch_bounds__(NT) void fused_kernel(const float* __restrict__ cls,
                                                   float4* __restrict__ out4,
                                                   int n4) {
    // ---------------- fill path ----------------
    if (blockIdx.x >= NC) {
        int fb = blockIdx.x - NC;
        const int ca4 = CA / 4;
        int stride = FILLB * NT;
        for (int i = fb * NT + threadIdx.x; i < n4; i += stride) {
            float v = (i >= ca4 && i < 2 * ca4) ? -1.0f : 0.0f;
            out4[i] = make_float4(v, v, v, v);
        }
        return;
    }

    // ---------------- NMS path ----------------
    const int c = blockIdx.x;
    const int tid = threadIdx.x;
    const int lane = tid & 31, wid = tid >> 5;

    __shared__ unsigned long long skey[SKEYN];      // 16KB (fallback: supp bitmap)
    __shared__ unsigned long long cmask64[NB];      // conflict rows (symmetric)
    __shared__ float4 bbox[NB];
    __shared__ float bar_[NB], bsc[NB];
    __shared__ int bidx[NB];
    __shared__ float4 kbox[MAXKEEP];
    __shared__ float kar[MAXKEEP], ksc[MAXKEEP];
    __shared__ int kid[MAXKEEP];
    __shared__ unsigned confParts[32];
    __shared__ unsigned long long alive64_s, km64_s;
    __shared__ unsigned long long red32[32];        // fallback warp-reduce
    __shared__ int kcount;

    unsigned* cmW = (unsigned*)cmask64;
    unsigned* kmW = (unsigned*)&km64_s;

    if (tid == 0) kcount = 0;
    __syncthreads();

    bool ok = (g_of == 0);
    if (ok) {
        for (int tier = 0; tier < NTIER; tier++) {
            if (kcount >= MAXKEEP) break;
            int n = g_cnt[tier][c];
            if (n > SKEYN) { ok = false; break; }
            if (n == 0) continue;

            // ---- load + pad + bitonic sort descending ----
            for (int i = tid; i < n; i += NT) skey[i] = g_cand[tier][c][i];
            int m = 1;
            while (m < n) m <<= 1;
            for (int i = n + tid; i < m; i += NT) skey[i] = 0ULL;
            __syncthreads();
            for (int k = 2; k <= m; k <<= 1) {
                for (int j = k >> 1; j > 0; j >>= 1) {
                    for (int i = tid; i < m; i += NT) {
                        int ixj = i ^ j;
                        if (ixj > i) {
                            bool desc = ((i & k) == 0);
                            unsigned long long A = skey[i], B2 = skey[ixj];
                            if (desc ? (A < B2) : (A > B2)) { skey[i] = B2; skey[ixj] = A; }
                        }
                    }
                    __syncthreads();
                }
            }

            // ---- batched walk, NB=64 ----
            for (int base = 0; base < n; base += NB) {
                if (kcount >= MAXKEEP) break;
                int nb = min(NB, n - base);

                if (tid < nb) {
                    unsigned long long key = skey[base + tid];
                    float s = __uint_as_float((unsigned)(key >> 32));
                    int idx = (int)(0xFFFFFFFFu - (unsigned)key);
                    float4 bb;
                    bb.x = g_boxes[idx * 4 + 0];
                    bb.y = g_boxes[idx * 4 + 1];
                    bb.z = g_boxes[idx * 4 + 2];
                    bb.w = g_boxes[idx * 4 + 3];
                    bbox[tid] = bb;
                    bar_[tid] = g_area[idx];
                    bsc[tid] = s;
                    bidx[tid] = idx;
                }
                __syncthreads();

                int i = tid & 63;
                int g = tid >> 6;  // 0..15
                bool have = i < nb;
                float4 mb = make_float4(0, 0, 0, 0);
                float ma = 0;
                if (have) { mb = bbox[i]; ma = bar_[i]; }

                // phase 1a: conflict vs kept list, 16-way split per candidate
                int kc = kcount;
                bool cfk = false;
                if (have) {
                    for (int j = g; j < kc; j += 16) {
                        float4 kb = kbox[j];
                        float ix1 = fmaxf(kb.x, mb.x), iy1 = fmaxf(kb.y, mb.y);
                        float ix2 = fminf(kb.z, mb.z), iy2 = fminf(kb.w, mb.w);
                        float inter = fmaxf(ix2 - ix1, 0.0f) * fmaxf(iy2 - iy1, 0.0f);
                        if (inter > 0.0f) {
                            float iou = inter / ((kar[j] + ma) - inter);
                            if (iou > 0.5f) { cfk = true; break; }
                        }
                    }
                }
                unsigned cb = __ballot_sync(FULLW, cfk);
                if (lane == 0) confParts[wid] = cb;
                __syncthreads();
                if (tid == 0) {
                    unsigned lo = 0, hi2 = 0;
                    #pragma unroll
                    for (int w = 0; w < 32; w += 2) { lo |= confParts[w]; hi2 |= confParts[w + 1]; }
                    unsigned long long conf = ((unsigned long long)hi2 << 32) | lo;
                    unsigned long long hv = (nb >= 64) ? ~0ULL : ((1ULL << nb) - 1ULL);
                    alive64_s = hv & ~conf;
                }
                __syncthreads();
                unsigned long long alive64 = alive64_s;

                // phase 1b: conflict matrix, 16 columns per ballot round
                for (int jb = 0; jb < nb; jb += 16) {
                    int j = jb + g;
                    bool cf = false;
                    if (have && j < nb && i != j) {
                        float4 jb4 = bbox[j];
                        float ja = bar_[j];
                        float ix1 = fmaxf(jb4.x, mb.x), iy1 = fmaxf(jb4.y, mb.y);
                        float ix2 = fminf(jb4.z, mb.z), iy2 = fminf(jb4.w, mb.w);
                        float inter = fmaxf(ix2 - ix1, 0.0f) * fmaxf(iy2 - iy1, 0.0f);
                        if (inter > 0.0f) {
                            float iou = inter / ((ja + ma) - inter);
                            cf = iou > 0.5f;
                        }
                    }
                    unsigned bits = __ballot_sync(FULLW, cf);
                    if (lane == 0 && j < nb) cmW[2 * j + (wid & 1)] = bits;
                }
                __syncthreads();

                // classify trivial/deferred (threads 0..63 = warps 0,1)
                {
                    bool trivial = false, deferred = false;
                    if (tid < 64) {
                        if ((alive64 >> tid) & 1ULL) {
                            unsigned long long below = (1ULL << tid) - 1ULL;
                            unsigned long long conf = cmask64[tid] & alive64 & below;
                            trivial = (conf == 0ULL);
                            deferred = !trivial;
                        }
                    }
                    unsigned tb = __ballot_sync(FULLW, trivial);
                    unsigned db = __ballot_sync(FULLW, deferred);
                    if (lane == 0 && wid < 2) kmW[wid] = tb;
                    if (lane == 1 && wid < 2) red32[wid] = db;  // stash deferred halves
                }
                __syncthreads();

                // thread 0: resolve deferred serially with 64-bit masks, truncate
                if (tid == 0) {
                    unsigned long long kw = km64_s;
                    unsigned long long dbits = ((unsigned long long)(unsigned)red32[1] << 32) |
                                               (unsigned)red32[0];
                    while (dbits) {
                        int q = __ffsll((long long)dbits) - 1;
                        dbits &= dbits - 1ULL;
                        unsigned long long below = (1ULL << q) - 1ULL;
                        if ((cmask64[q] & kw & below) == 0ULL) kw |= (1ULL << q);
                    }
                    int rem = MAXKEEP - kcount;
                    int p = __popcll(kw);
                    while (p > rem) {
                        kw &= ~(0x8000000000000000ULL >> __clzll((long long)kw));
                        p--;
                    }
                    km64_s = kw;
                }
                __syncthreads();

                unsigned long long kw = km64_s;
                int kc0 = kcount;
                if (tid < 64 && ((kw >> tid) & 1ULL)) {
                    int pos = kc0 + __popcll(kw & ((1ULL << tid) - 1ULL));
                    kbox[pos] = bbox[tid];
                    kar[pos] = bar_[tid];
                    ksc[pos] = bsc[tid];
                    kid[pos] = bidx[tid];
                }
                __syncthreads();
                if (tid == 0) kcount = kc0 + __popcll(kw);
                __syncthreads();
            }
        }
    }
    __syncthreads();

    // ---- Exact fallback (never triggered for this data) ----
    if (!ok || kcount < MAXKEEP) {
        unsigned* supp = (unsigned*)skey;  // 9.6KB of 16KB
        const int NW = (AN + 31) / 32;
        for (int w2 = tid; w2 < NW; w2 += NT) supp[w2] = 0u;
        if (tid == 0) kcount = 0;
        __syncthreads();
        for (int it = 0; it < MAXKEEP; it++) {
            unsigned long long best = 0ULL;
            for (int i = tid; i < AN; i += NT) {
                if (!((supp[i >> 5] >> (i & 31)) & 1u)) {
                    float s = cls[i * NC + c];
                    if (s > 0.1f) {
                        unsigned long long k =
                            ((unsigned long long)__float_as_uint(s) << 32) |
                            (unsigned long long)(0xFFFFFFFFu - (unsigned)i);
                        if (k > best) best = k;
                    }
                }
            }
            #pragma unroll
            for (int off = 16; off > 0; off >>= 1) {
                unsigned long long o = __shfl_down_sync(FULLW, best, off);
                if (o > best) best = o;
            }
            if (lane == 0) red32[wid] = best;
            __syncthreads();
            if (tid == 0) {
                unsigned long long b2 = red32[0];
                for (int w = 1; w < 32; w++)
                    if (red32[w] > b2) b2 = red32[w];
                red32[0] = b2;
            }
            __syncthreads();
            unsigned long long bk = red32[0];
            __syncthreads();
            if (bk == 0ULL) break;
            int bi = (int)(0xFFFFFFFFu - (unsigned)bk);
            float s = __uint_as_float((unsigned)(bk >> 32));
            float zx1 = g_boxes[bi * 4 + 0], zy1 = g_boxes[bi * 4 + 1];
            float zx2 = g_boxes[bi * 4 + 2], zy2 = g_boxes[bi * 4 + 3];
            float za = g_area[bi];
            if (tid == 0) {
                int kc2 = kcount;
                kbox[kc2] = make_float4(zx1, zy1, zx2, zy2);
                kar[kc2] = za; ksc[kc2] = s; kid[kc2] = bi;
                kcount = kc2 + 1;
            }
            for (int i = tid; i < AN; i += NT) {
                float ix1 = fmaxf(zx1, g_boxes[i * 4 + 0]);
                float iy1 = fmaxf(zy1, g_boxes[i * 4 + 1]);
                float ix2 = fminf(zx2, g_boxes[i * 4 + 2]);
                float iy2 = fminf(zy2, g_boxes[i * 4 + 3]);
                float inter = fmaxf(ix2 - ix1, 0.0f) * fmaxf(iy2 - iy1, 0.0f);
                float iou = inter / ((za + g_area[i]) - inter);
                if (iou > 0.5f || i == bi) atomicOr(&supp[i >> 5], 1u << (i & 31));
            }
            __syncthreads();
        }
        __syncthreads();
    }

    // ---- write compact results to device globals ----
    int kc = kcount;
    if (tid == 0) g_kcnt[c] = kc;
    for (int t = tid; t < kc; t += NT) {
        g_kboxg[c][t] = kbox[t];
        g_kscg[c][t] = ksc[t];
        g_kidg[c][t] = kid[t];
    }
}

// ---------------------------------------------------------------------------
extern "C" void kernel_launch(void* const* d_in, const int* in_sizes, int n_in,
                              void* d_out, int out_size) {
    const float* classification = (const float*)d_in[0];  // [1, A, C]
    const float* regression = (const float*)d_in[1];      // [1, A, 4]
    const float* anchors = (const float*)d_in[2];         // [A, 4]
    float* out = (float*)d_out;

    prep_kernel<<<PREPB, 256>>>(classification, anchors, regression);

    int n4 = out_size / 4;
    fused_kernel<<<NC + FILLB, NT>>>(classification, (float4*)out, n4);

    scatter_kernel<<<NC, 256>>>(out);  // also resets g_cnt/g_of for next call
}